// round 1
// baseline (speedup 1.0000x reference)
#include <cuda_runtime.h>
#include <math_constants.h>

#define NN   20000
#define KDIM 9480
#define GEDIM 128
#define TR   64
#define BK   8

// Scratch for router output h[N, 128] (10.24 MB) — static __device__, no allocs.
__device__ float g_h[(size_t)NN * GEDIM];

__device__ __forceinline__ void fma2(unsigned long long &d,
                                     unsigned long long a,
                                     unsigned long long b) {
    asm("fma.rn.f32x2 %0, %1, %2, %0;" : "+l"(d) : "l"(a), "l"(b));
}

// ---------------------------------------------------------------------------
// Kernel 1: router GEMM  h = x @ Wr + br   (fp32, f32x2 packed FMA)
// Tile: 64 rows x 128 cols, BK=8, 256 threads, 4x4(float2) micro-tile.
// A is stored duplicated in smem (float2{v,v}) so the broadcast multiplier
// can be loaded directly as a 64-bit operand for fma.rn.f32x2.
// ---------------------------------------------------------------------------
__global__ void __launch_bounds__(256) router_gemm_kernel(
    const float* __restrict__ x,
    const float* __restrict__ Wr,
    const float* __restrict__ br)
{
    __shared__ float2 Asd[BK][TR];     // duplicated A: 4 KB
    __shared__ float  Bs[BK][GEDIM];   // 4 KB

    const int tid  = threadIdx.x;
    const int row0 = blockIdx.x * TR;

    // A-load mapping (threads 0..127): row = tid/2, quad = (tid&1)*4
    const int arow = tid >> 1;
    const int aq   = (tid & 1) * 4;
    // B-load mapping (all 256): k = tid/32, col = (tid&31)*4
    const int bkr  = tid >> 5;
    const int bcol = (tid & 31) * 4;

    const int ty = tid >> 4;   // 0..15 -> rows ty*4 .. ty*4+3
    const int tx = tid & 15;   // 0..15 -> cols tx*8 .. tx*8+7

    unsigned long long acc[4][4];
#pragma unroll
    for (int i = 0; i < 4; i++)
#pragma unroll
        for (int j = 0; j < 4; j++) acc[i][j] = 0ull;

    const bool aActive = tid < 128;
    const bool aOk = aActive && (row0 + arow < NN);
    const float* xptr = x + (size_t)(row0 + arow) * KDIM + aq;

    for (int k0 = 0; k0 < KDIM; k0 += BK) {
        float4 av = make_float4(0.f, 0.f, 0.f, 0.f);
        if (aOk) av = *reinterpret_cast<const float4*>(xptr + k0);
        float4 bvv = *reinterpret_cast<const float4*>(
            Wr + (size_t)(k0 + bkr) * GEDIM + bcol);

        if (aActive) {
            Asd[aq + 0][arow] = make_float2(av.x, av.x);
            Asd[aq + 1][arow] = make_float2(av.y, av.y);
            Asd[aq + 2][arow] = make_float2(av.z, av.z);
            Asd[aq + 3][arow] = make_float2(av.w, av.w);
        }
        *reinterpret_cast<float4*>(&Bs[bkr][bcol]) = bvv;
        __syncthreads();

#pragma unroll
        for (int kk = 0; kk < BK; kk++) {
            unsigned long long a2[4], b2[4];
#pragma unroll
            for (int i = 0; i < 4; i++)
                a2[i] = *reinterpret_cast<const unsigned long long*>(
                    &Asd[kk][ty * 4 + i]);
#pragma unroll
            for (int j = 0; j < 4; j++)
                b2[j] = *reinterpret_cast<const unsigned long long*>(
                    &Bs[kk][tx * 8 + 2 * j]);
#pragma unroll
            for (int i = 0; i < 4; i++)
#pragma unroll
                for (int j = 0; j < 4; j++)
                    fma2(acc[i][j], a2[i], b2[j]);
        }
        __syncthreads();
    }

#pragma unroll
    for (int i = 0; i < 4; i++) {
        const int row = row0 + ty * 4 + i;
        if (row < NN) {
#pragma unroll
            for (int j = 0; j < 4; j++) {
                float2 r = *reinterpret_cast<float2*>(&acc[i][j]);
                const int col = tx * 8 + 2 * j;
                float2 o;
                o.x = r.x + br[col];
                o.y = r.y + br[col + 1];
                *reinterpret_cast<float2*>(&g_h[(size_t)row * GEDIM + col]) = o;
            }
        }
    }
}

// ---------------------------------------------------------------------------
// Kernel 2: per-sample epilogue. One warp per sample.
// Key insight: prediction = w1*out[g1,f1] + w2*out[g2,f2], so only the two
// selected experts' groups need computing. Half-warp per selected expert.
// ---------------------------------------------------------------------------
__global__ void __launch_bounds__(256) epilogue_kernel(
    const float* __restrict__ We, const float* __restrict__ be,
    const float* __restrict__ Wq, const float* __restrict__ bq,
    const float* __restrict__ Wk, const float* __restrict__ bk,
    const float* __restrict__ Wv, const float* __restrict__ bv,
    const float* __restrict__ Wo, const float* __restrict__ bo,
    float* __restrict__ out)
{
    __shared__ float hs_s[8][GEDIM];
    __shared__ float eoS[8][32], qS[8][32], kS[8][32], vS[8][32],
                     aS[8][32], atS[8][32];

    const int warp = threadIdx.x >> 5;
    const int lane = threadIdx.x & 31;
    const int n = blockIdx.x * 8 + warp;
    if (n >= NN) return;

    float* hs = hs_s[warp];

    // load h row (128 floats): lane handles 4 contiguous
    float4 hv = *reinterpret_cast<const float4*>(
        &g_h[(size_t)n * GEDIM + lane * 4]);
    *reinterpret_cast<float4*>(&hs[lane * 4]) = hv;

    float v[4] = {hv.x, hv.y, hv.z, hv.w};

    // ---- top-1 (argmax, min-index on ties) ----
    float bval = v[0];
    int bidx = lane * 4;
#pragma unroll
    for (int t = 1; t < 4; t++)
        if (v[t] > bval) { bval = v[t]; bidx = lane * 4 + t; }
#pragma unroll
    for (int off = 16; off >= 1; off >>= 1) {
        float ov = __shfl_xor_sync(0xffffffffu, bval, off);
        int   oi = __shfl_xor_sync(0xffffffffu, bidx, off);
        if (ov > bval || (ov == bval && oi < bidx)) { bval = ov; bidx = oi; }
    }
    const float m1 = bval;
    const int   i1 = bidx;

    // ---- top-2 (exclude i1) ----
    bval = -CUDART_INF_F;
    bidx = 1 << 30;
#pragma unroll
    for (int t = 0; t < 4; t++) {
        const int idx = lane * 4 + t;
        if (idx != i1 && v[t] > bval) { bval = v[t]; bidx = idx; }
    }
#pragma unroll
    for (int off = 16; off >= 1; off >>= 1) {
        float ov = __shfl_xor_sync(0xffffffffu, bval, off);
        int   oi = __shfl_xor_sync(0xffffffffu, bidx, off);
        if (ov > bval || (ov == bval && oi < bidx)) { bval = ov; bidx = oi; }
    }
    const float m2 = bval;
    const int   i2 = bidx;

    // gating softmax over {m1, m2}
    const float e2v = __expf(m2 - m1);
    const float inv = 1.0f / (1.0f + e2v);
    const float w1 = inv, w2 = e2v * inv;

    const int side   = lane >> 4;      // 0: top-1 expert, 1: top-2 expert
    const int l      = lane & 15;
    const int target = side ? i2 : i1;
    const float wsel = side ? w2 : w1;
    const int g = target >> 4;         // group
    const int f = target & 15;         // expert within group

    __syncwarp();

    // ---- eo[e] for all 16 experts of group g (lane l computes expert l) ----
    {
        const float4* h4 = reinterpret_cast<const float4*>(hs);
        const float4* w4 = reinterpret_cast<const float4*>(
            We + (size_t)(g * 16 + l) * GEDIM);
        float acc = be[g * 16 + l];
#pragma unroll 8
        for (int kq = 0; kq < GEDIM / 4; kq++) {
            float4 hq = h4[kq];
            float4 wq = w4[kq];
            acc += hq.x * wq.x + hq.y * wq.y + hq.z * wq.z + hq.w * wq.w;
        }
        eoS[warp][lane] = acc;
    }
    __syncwarp();

    // ---- Q/K/V projections: y[f] = sum_e eo[e] * W[g,f,e] + b[g,f] ----
    {
        const float* wqr = Wq + (size_t)(g * 16 + l) * 16;
        const float* wkr = Wk + (size_t)(g * 16 + l) * 16;
        const float* wvr = Wv + (size_t)(g * 16 + l) * 16;
        float q  = bq[g * 16 + l];
        float kk = bk[g * 16 + l];
        float vv = bv[g * 16 + l];
#pragma unroll
        for (int e = 0; e < 16; e++) {
            const float eo = eoS[warp][side * 16 + e];
            q  += eo * wqr[e];
            kk += eo * wkr[e];
            vv += eo * wvr[e];
        }
        qS[warp][lane] = q;
        kS[warp][lane] = kk;
        vS[warp][lane] = vv;
    }
    __syncwarp();

    // ---- scores + softmax: lane l handles (d = l/4, e = l%4) ----
    // Qh[d,h] = q[h*4+d]; scores[d,e] = sum_h Qh[d,h]*Kh[e,h] / 2
    {
        const int d = l >> 2, e = l & 3;
        float s = 0.f;
#pragma unroll
        for (int h = 0; h < 4; h++)
            s += qS[warp][side * 16 + h * 4 + d] *
                 kS[warp][side * 16 + h * 4 + e];
        s *= 0.5f;
        float mx = s;
        mx = fmaxf(mx, __shfl_xor_sync(0xffffffffu, mx, 1));
        mx = fmaxf(mx, __shfl_xor_sync(0xffffffffu, mx, 2));
        float p = __expf(s - mx);
        float sm = p;
        sm += __shfl_xor_sync(0xffffffffu, sm, 1);
        sm += __shfl_xor_sync(0xffffffffu, sm, 2);
        p /= sm;
        aS[warp][lane] = p;  // attn[d,e]
    }
    __syncwarp();

    // ---- att_flat[h*4+d] = sum_e attn[d,e] * v[h*4+e] ----
    {
        const int h_ = l >> 2, dd = l & 3;
        float att = 0.f;
#pragma unroll
        for (int e = 0; e < 4; e++)
            att += aS[warp][side * 16 + dd * 4 + e] *
                   vS[warp][side * 16 + h_ * 4 + e];
        atS[warp][lane] = att;
    }
    __syncwarp();

    // ---- out[f] = sum_e att_flat[e] * Wo[g,f,e] + bo; reduce over half-warp
    {
        const float* wor = Wo + (size_t)(g * 16 + f) * 16;
        float t = atS[warp][side * 16 + l] * wor[l];
#pragma unroll
        for (int off = 8; off >= 1; off >>= 1)
            t += __shfl_xor_sync(0xffffffffu, t, off);
        t += bo[g * 16 + f];
        const float res = wsel * t;
        const float tot = res + __shfl_xor_sync(0xffffffffu, res, 16);
        if (lane == 0) out[n] = tot;
    }
}

extern "C" void kernel_launch(void* const* d_in, const int* in_sizes, int n_in,
                              void* d_out, int out_size)
{
    const float* x  = (const float*)d_in[0];
    const float* Wr = (const float*)d_in[1];
    const float* br = (const float*)d_in[2];
    const float* We = (const float*)d_in[3];
    const float* be = (const float*)d_in[4];
    const float* Wq = (const float*)d_in[5];
    const float* bq = (const float*)d_in[6];
    const float* Wk = (const float*)d_in[7];
    const float* bk = (const float*)d_in[8];
    const float* Wv = (const float*)d_in[9];
    const float* bv = (const float*)d_in[10];
    const float* Wo = (const float*)d_in[11];
    const float* bo = (const float*)d_in[12];
    float* out = (float*)d_out;

    router_gemm_kernel<<<(NN + TR - 1) / TR, 256>>>(x, Wr, br);
    epilogue_kernel<<<(NN + 7) / 8, 256>>>(We, be, Wq, bq, Wk, bk,
                                           Wv, bv, Wo, bo, out);
}

// round 2
// speedup vs baseline: 1.0003x; 1.0003x over previous
#include <cuda_runtime.h>
#include <math_constants.h>

#define NN   20000
#define KDIM 9480
#define GEDIM 128
#define TR   64
#define BK   8

// Scratch for router output h[N, 128] (10.24 MB) — static __device__, no allocs.
__device__ float g_h[(size_t)NN * GEDIM];

__device__ __forceinline__ void fma2(unsigned long long &d,
                                     unsigned long long a,
                                     unsigned long long b) {
    asm("fma.rn.f32x2 %0, %1, %2, %0;" : "+l"(d) : "l"(a), "l"(b));
}

// ---------------------------------------------------------------------------
// Kernel 1: router GEMM  h = x @ Wr + br   (fp32, f32x2 packed FMA)
// Tile: 64 rows x 128 cols, BK=8, 256 threads, 4x4(float2) micro-tile.
// A is stored duplicated in smem (float2{v,v}) so the broadcast multiplier
// can be loaded directly as a 64-bit operand for fma.rn.f32x2.
// ---------------------------------------------------------------------------
__global__ void __launch_bounds__(256) router_gemm_kernel(
    const float* __restrict__ x,
    const float* __restrict__ Wr,
    const float* __restrict__ br)
{
    __shared__ float2 Asd[BK][TR];     // duplicated A: 4 KB
    __shared__ float  Bs[BK][GEDIM];   // 4 KB

    const int tid  = threadIdx.x;
    const int row0 = blockIdx.x * TR;

    // A-load mapping (threads 0..127): row = tid/2, quad = (tid&1)*4
    const int arow = tid >> 1;
    const int aq   = (tid & 1) * 4;
    // B-load mapping (all 256): k = tid/32, col = (tid&31)*4
    const int bkr  = tid >> 5;
    const int bcol = (tid & 31) * 4;

    const int ty = tid >> 4;   // 0..15 -> rows ty*4 .. ty*4+3
    const int tx = tid & 15;   // 0..15 -> cols tx*8 .. tx*8+7

    unsigned long long acc[4][4];
#pragma unroll
    for (int i = 0; i < 4; i++)
#pragma unroll
        for (int j = 0; j < 4; j++) acc[i][j] = 0ull;

    const bool aActive = tid < 128;
    const bool aOk = aActive && (row0 + arow < NN);
    const float* xptr = x + (size_t)(row0 + arow) * KDIM + aq;

    for (int k0 = 0; k0 < KDIM; k0 += BK) {
        float4 av = make_float4(0.f, 0.f, 0.f, 0.f);
        if (aOk) av = *reinterpret_cast<const float4*>(xptr + k0);
        float4 bvv = *reinterpret_cast<const float4*>(
            Wr + (size_t)(k0 + bkr) * GEDIM + bcol);

        if (aActive) {
            Asd[aq + 0][arow] = make_float2(av.x, av.x);
            Asd[aq + 1][arow] = make_float2(av.y, av.y);
            Asd[aq + 2][arow] = make_float2(av.z, av.z);
            Asd[aq + 3][arow] = make_float2(av.w, av.w);
        }
        *reinterpret_cast<float4*>(&Bs[bkr][bcol]) = bvv;
        __syncthreads();

#pragma unroll
        for (int kk = 0; kk < BK; kk++) {
            unsigned long long a2[4], b2[4];
#pragma unroll
            for (int i = 0; i < 4; i++)
                a2[i] = *reinterpret_cast<const unsigned long long*>(
                    &Asd[kk][ty * 4 + i]);
#pragma unroll
            for (int j = 0; j < 4; j++)
                b2[j] = *reinterpret_cast<const unsigned long long*>(
                    &Bs[kk][tx * 8 + 2 * j]);
#pragma unroll
            for (int i = 0; i < 4; i++)
#pragma unroll
                for (int j = 0; j < 4; j++)
                    fma2(acc[i][j], a2[i], b2[j]);
        }
        __syncthreads();
    }

#pragma unroll
    for (int i = 0; i < 4; i++) {
        const int row = row0 + ty * 4 + i;
        if (row < NN) {
#pragma unroll
            for (int j = 0; j < 4; j++) {
                float2 r = *reinterpret_cast<float2*>(&acc[i][j]);
                const int col = tx * 8 + 2 * j;
                float2 o;
                o.x = r.x + br[col];
                o.y = r.y + br[col + 1];
                *reinterpret_cast<float2*>(&g_h[(size_t)row * GEDIM + col]) = o;
            }
        }
    }
}

// ---------------------------------------------------------------------------
// Kernel 2: per-sample epilogue. One warp per sample.
// Key insight: prediction = w1*out[g1,f1] + w2*out[g2,f2], so only the two
// selected experts' groups need computing. Half-warp per selected expert.
// ---------------------------------------------------------------------------
__global__ void __launch_bounds__(256) epilogue_kernel(
    const float* __restrict__ We, const float* __restrict__ be,
    const float* __restrict__ Wq, const float* __restrict__ bq,
    const float* __restrict__ Wk, const float* __restrict__ bk,
    const float* __restrict__ Wv, const float* __restrict__ bv,
    const float* __restrict__ Wo, const float* __restrict__ bo,
    float* __restrict__ out)
{
    __shared__ float hs_s[8][GEDIM];
    __shared__ float eoS[8][32], qS[8][32], kS[8][32], vS[8][32],
                     aS[8][32], atS[8][32];

    const int warp = threadIdx.x >> 5;
    const int lane = threadIdx.x & 31;
    const int n = blockIdx.x * 8 + warp;
    if (n >= NN) return;

    float* hs = hs_s[warp];

    // load h row (128 floats): lane handles 4 contiguous
    float4 hv = *reinterpret_cast<const float4*>(
        &g_h[(size_t)n * GEDIM + lane * 4]);
    *reinterpret_cast<float4*>(&hs[lane * 4]) = hv;

    float v[4] = {hv.x, hv.y, hv.z, hv.w};

    // ---- top-1 (argmax, min-index on ties) ----
    float bval = v[0];
    int bidx = lane * 4;
#pragma unroll
    for (int t = 1; t < 4; t++)
        if (v[t] > bval) { bval = v[t]; bidx = lane * 4 + t; }
#pragma unroll
    for (int off = 16; off >= 1; off >>= 1) {
        float ov = __shfl_xor_sync(0xffffffffu, bval, off);
        int   oi = __shfl_xor_sync(0xffffffffu, bidx, off);
        if (ov > bval || (ov == bval && oi < bidx)) { bval = ov; bidx = oi; }
    }
    const float m1 = bval;
    const int   i1 = bidx;

    // ---- top-2 (exclude i1) ----
    bval = -CUDART_INF_F;
    bidx = 1 << 30;
#pragma unroll
    for (int t = 0; t < 4; t++) {
        const int idx = lane * 4 + t;
        if (idx != i1 && v[t] > bval) { bval = v[t]; bidx = idx; }
    }
#pragma unroll
    for (int off = 16; off >= 1; off >>= 1) {
        float ov = __shfl_xor_sync(0xffffffffu, bval, off);
        int   oi = __shfl_xor_sync(0xffffffffu, bidx, off);
        if (ov > bval || (ov == bval && oi < bidx)) { bval = ov; bidx = oi; }
    }
    const float m2 = bval;
    const int   i2 = bidx;

    // gating softmax over {m1, m2}
    const float e2v = __expf(m2 - m1);
    const float inv = 1.0f / (1.0f + e2v);
    const float w1 = inv, w2 = e2v * inv;

    const int side   = lane >> 4;      // 0: top-1 expert, 1: top-2 expert
    const int l      = lane & 15;
    const int target = side ? i2 : i1;
    const float wsel = side ? w2 : w1;
    const int g = target >> 4;         // group
    const int f = target & 15;         // expert within group

    __syncwarp();

    // ---- eo[e] for all 16 experts of group g (lane l computes expert l) ----
    {
        const float4* h4 = reinterpret_cast<const float4*>(hs);
        const float4* w4 = reinterpret_cast<const float4*>(
            We + (size_t)(g * 16 + l) * GEDIM);
        float acc = be[g * 16 + l];
#pragma unroll 8
        for (int kq = 0; kq < GEDIM / 4; kq++) {
            float4 hq = h4[kq];
            float4 wq = w4[kq];
            acc += hq.x * wq.x + hq.y * wq.y + hq.z * wq.z + hq.w * wq.w;
        }
        eoS[warp][lane] = acc;
    }
    __syncwarp();

    // ---- Q/K/V projections: y[f] = sum_e eo[e] * W[g,f,e] + b[g,f] ----
    {
        const float* wqr = Wq + (size_t)(g * 16 + l) * 16;
        const float* wkr = Wk + (size_t)(g * 16 + l) * 16;
        const float* wvr = Wv + (size_t)(g * 16 + l) * 16;
        float q  = bq[g * 16 + l];
        float kk = bk[g * 16 + l];
        float vv = bv[g * 16 + l];
#pragma unroll
        for (int e = 0; e < 16; e++) {
            const float eo = eoS[warp][side * 16 + e];
            q  += eo * wqr[e];
            kk += eo * wkr[e];
            vv += eo * wvr[e];
        }
        qS[warp][lane] = q;
        kS[warp][lane] = kk;
        vS[warp][lane] = vv;
    }
    __syncwarp();

    // ---- scores + softmax: lane l handles (d = l/4, e = l%4) ----
    // Qh[d,h] = q[h*4+d]; scores[d,e] = sum_h Qh[d,h]*Kh[e,h] / 2
    {
        const int d = l >> 2, e = l & 3;
        float s = 0.f;
#pragma unroll
        for (int h = 0; h < 4; h++)
            s += qS[warp][side * 16 + h * 4 + d] *
                 kS[warp][side * 16 + h * 4 + e];
        s *= 0.5f;
        float mx = s;
        mx = fmaxf(mx, __shfl_xor_sync(0xffffffffu, mx, 1));
        mx = fmaxf(mx, __shfl_xor_sync(0xffffffffu, mx, 2));
        float p = __expf(s - mx);
        float sm = p;
        sm += __shfl_xor_sync(0xffffffffu, sm, 1);
        sm += __shfl_xor_sync(0xffffffffu, sm, 2);
        p /= sm;
        aS[warp][lane] = p;  // attn[d,e]
    }
    __syncwarp();

    // ---- att_flat[h*4+d] = sum_e attn[d,e] * v[h*4+e] ----
    {
        const int h_ = l >> 2, dd = l & 3;
        float att = 0.f;
#pragma unroll
        for (int e = 0; e < 4; e++)
            att += aS[warp][side * 16 + dd * 4 + e] *
                   vS[warp][side * 16 + h_ * 4 + e];
        atS[warp][lane] = att;
    }
    __syncwarp();

    // ---- out[f] = sum_e att_flat[e] * Wo[g,f,e] + bo; reduce over half-warp
    {
        const float* wor = Wo + (size_t)(g * 16 + f) * 16;
        float t = atS[warp][side * 16 + l] * wor[l];
#pragma unroll
        for (int off = 8; off >= 1; off >>= 1)
            t += __shfl_xor_sync(0xffffffffu, t, off);
        t += bo[g * 16 + f];
        const float res = wsel * t;
        const float tot = res + __shfl_xor_sync(0xffffffffu, res, 16);
        if (lane == 0) out[n] = tot;
    }
}

extern "C" void kernel_launch(void* const* d_in, const int* in_sizes, int n_in,
                              void* d_out, int out_size)
{
    const float* x  = (const float*)d_in[0];
    const float* Wr = (const float*)d_in[1];
    const float* br = (const float*)d_in[2];
    const float* We = (const float*)d_in[3];
    const float* be = (const float*)d_in[4];
    const float* Wq = (const float*)d_in[5];
    const float* bq = (const float*)d_in[6];
    const float* Wk = (const float*)d_in[7];
    const float* bk = (const float*)d_in[8];
    const float* Wv = (const float*)d_in[9];
    const float* bv = (const float*)d_in[10];
    const float* Wo = (const float*)d_in[11];
    const float* bo = (const float*)d_in[12];
    float* out = (float*)d_out;

    router_gemm_kernel<<<(NN + TR - 1) / TR, 256>>>(x, Wr, br);
    epilogue_kernel<<<(NN + 7) / 8, 256>>>(We, be, Wq, bq, Wk, bk,
                                           Wv, bv, Wo, bo, out);
}

// round 4
// speedup vs baseline: 4.3440x; 4.3426x over previous
#include <cuda_runtime.h>
#include <cuda_fp16.h>
#include <math_constants.h>
#include <cstdint>

#define NN    20000
#define KDIM  9480
#define GEDIM 128
#define NCH   149          // ceil(9480/64)
#define TILEB 16384        // one 128x64-half tile, bytes
#define STAGEB 65536       // 4 tiles per stage
#define GEMM_SMEM (1024 + 2 * STAGEB)

// ---------------- static device scratch (no allocs) ----------------
__device__ float  g_hp[4][(size_t)NN * GEDIM];     // partial h per K-split
__device__ __half g_Bhi[(size_t)NCH * 8192];       // Wr^T hi, pre-swizzled chunks
__device__ __half g_Blo[(size_t)NCH * 8192];       // Wr^T lo

// ---------------- helpers ----------------
__device__ __forceinline__ uint32_t smem_u32(const void* p) {
    uint32_t a;
    asm("{ .reg .u64 t; cvta.to.shared.u64 t, %1; cvt.u32.u64 %0, t; }"
        : "=r"(a) : "l"(p));
    return a;
}
__device__ __forceinline__ uint32_t swz(uint32_t b) { return b ^ ((b >> 3) & 0x70); }

__device__ __forceinline__ void ldsm4(uint32_t& r0, uint32_t& r1,
                                      uint32_t& r2, uint32_t& r3, uint32_t a) {
    asm volatile("ldmatrix.sync.aligned.m8n8.x4.shared.b16 {%0,%1,%2,%3}, [%4];"
                 : "=r"(r0), "=r"(r1), "=r"(r2), "=r"(r3) : "r"(a));
}
__device__ __forceinline__ void mma16816(float* c, const uint32_t* a,
                                         const uint32_t* b) {
    asm volatile(
        "mma.sync.aligned.m16n8k16.row.col.f32.f16.f16.f32 "
        "{%0,%1,%2,%3},{%4,%5,%6,%7},{%8,%9},{%0,%1,%2,%3};"
        : "+f"(c[0]), "+f"(c[1]), "+f"(c[2]), "+f"(c[3])
        : "r"(a[0]), "r"(a[1]), "r"(a[2]), "r"(a[3]), "r"(b[0]), "r"(b[1]));
}
#define CP16(dst, src) \
    asm volatile("cp.async.ca.shared.global [%0], [%1], 16;" \
                 :: "r"(dst), "l"(src) : "memory")
#define CP_COMMIT() asm volatile("cp.async.commit_group;" ::: "memory")
#define CP_WAIT1()  asm volatile("cp.async.wait_group 1;" ::: "memory")
#define CP_WAIT0()  asm volatile("cp.async.wait_group 0;" ::: "memory")

union U8h { __half h[8]; uint4 u; };

// ---------------------------------------------------------------------------
// Prep: g_Bhi/g_Blo = transpose(Wr)*1024, split hi/lo, per-chunk swizzled
// 128(n) x 64(k) half tiles. One block per chunk.
// ---------------------------------------------------------------------------
__global__ void __launch_bounds__(256) prep_kernel(const float* __restrict__ Wr)
{
    __shared__ float Ws[64][128];
    const int c = blockIdx.x;
    const int tid = threadIdx.x;

    for (int i = tid; i < 64 * 32; i += 256) {
        const int r = i >> 5;
        const int col = (i & 31) * 4;
        const int gk = c * 64 + r;
        float4 v = make_float4(0.f, 0.f, 0.f, 0.f);
        if (gk < KDIM) v = *reinterpret_cast<const float4*>(Wr + (size_t)gk * GEDIM + col);
        Ws[r][col] = v.x; Ws[r][col + 1] = v.y; Ws[r][col + 2] = v.z; Ws[r][col + 3] = v.w;
    }
    __syncthreads();

    const int n = tid & 127;
    const int sel = tid >> 7;     // 0 -> hi, 1 -> lo
    char* dstBase = reinterpret_cast<char*>(sel ? g_Blo : g_Bhi) + (size_t)c * TILEB;

    for (int grp = 0; grp < 8; grp++) {
        U8h u;
#pragma unroll
        for (int j = 0; j < 8; j++) {
            const float f = Ws[grp * 8 + j][n] * 1024.0f;
            const __half hi = __float2half_rn(f);
            u.h[j] = sel ? __float2half_rn(f - __half2float(hi)) : hi;
        }
        const uint32_t byte = (uint32_t)n * 128 + grp * 16;
        *reinterpret_cast<uint4*>(dstBase + swz(byte)) = u.u;
    }
}

// ---------------------------------------------------------------------------
// GEMM via mma.sync m16n8k16, fp16 3-product split, fp32 accum.
// grid (157, 4); 512 threads; 128x128 tile; K chunks of 64; 2-stage pipeline.
// Stage layout: Ahi(16K) Alo(16K) Bhi(16K) Blo(16K).
// ---------------------------------------------------------------------------
__global__ void __launch_bounds__(512) gemm_kernel(const float* __restrict__ x)
{
    extern __shared__ char smem[];
    const uint32_t sb = smem_u32(smem) + 1024;
    char* const stg0 = smem + 1024;

    const int tid  = threadIdx.x;
    const int wid  = tid >> 5;
    const int lane = tid & 31;
    const int wm   = wid & 3;         // M quadrant (32 rows)
    const int wn   = wid >> 2;        // N quadrant (32 cols)
    const int m0   = blockIdx.x * 128;
    const int split = blockIdx.y;
    const int c0 = split * 38;
    const int c1 = (c0 + 38 < NCH) ? c0 + 38 : NCH;
    const int nrel = c1 - c0;

    // A producer mapping: 512 threads -> 128 rows x 4 k-quarters (16 halves)
    const int arow = tid >> 2;
    const int aq   = tid & 3;
    const bool rowOk = (m0 + arow) < NN;
    const float* xrow = x + (size_t)(m0 + arow) * KDIM;

    // B producer mapping: 32B of hi + 32B of lo per thread
    const uint32_t bOffH = (uint32_t)tid * 32;

    float acc[2][4][4];
#pragma unroll
    for (int i = 0; i < 2; i++)
#pragma unroll
        for (int j = 0; j < 4; j++)
#pragma unroll
            for (int q = 0; q < 4; q++) acc[i][j][q] = 0.f;

    // ---- prologue: B(c0) cp.async, A(c0) LDG ----
    {
        const char* srcH = reinterpret_cast<const char*>(g_Bhi) + (size_t)c0 * TILEB + bOffH;
        const char* srcL = reinterpret_cast<const char*>(g_Blo) + (size_t)c0 * TILEB + bOffH;
        CP16(sb + 2 * TILEB + bOffH,      srcH);
        CP16(sb + 2 * TILEB + bOffH + 16, srcH + 16);
        CP16(sb + 3 * TILEB + bOffH,      srcL);
        CP16(sb + 3 * TILEB + bOffH + 16, srcL + 16);
        CP_COMMIT();
    }
    float4 ar[4];
    {
        const int kb = c0 * 64 + aq * 16;
#pragma unroll
        for (int j = 0; j < 4; j++) {
            ar[j] = make_float4(0.f, 0.f, 0.f, 0.f);
            if (rowOk && kb + j * 4 < KDIM)
                ar[j] = *reinterpret_cast<const float4*>(xrow + kb + j * 4);
        }
    }

    for (int rc = 0; rc < nrel; ++rc) {
        const int s = rc & 1;
        const uint32_t stBase = sb + s * STAGEB;
        char* const stPtr = stg0 + s * STAGEB;
        const bool hasNext = (rc + 1) < nrel;

        float4 arN[4];
        if (hasNext) {
            const int cn = c0 + rc + 1;
            const uint32_t st2 = sb + (s ^ 1) * STAGEB;
            const char* srcH = reinterpret_cast<const char*>(g_Bhi) + (size_t)cn * TILEB + bOffH;
            const char* srcL = reinterpret_cast<const char*>(g_Blo) + (size_t)cn * TILEB + bOffH;
            CP16(st2 + 2 * TILEB + bOffH,      srcH);
            CP16(st2 + 2 * TILEB + bOffH + 16, srcH + 16);
            CP16(st2 + 3 * TILEB + bOffH,      srcL);
            CP16(st2 + 3 * TILEB + bOffH + 16, srcL + 16);
            CP_COMMIT();
            const int kb = cn * 64 + aq * 16;
#pragma unroll
            for (int j = 0; j < 4; j++) {
                arN[j] = make_float4(0.f, 0.f, 0.f, 0.f);
                if (rowOk && kb + j * 4 < KDIM)
                    arN[j] = *reinterpret_cast<const float4*>(xrow + kb + j * 4);
            }
        }

        // ---- STS A(rc): split fp32 -> fp16 hi/lo, swizzled ----
        {
            const float* vf = reinterpret_cast<const float*>(ar);
#pragma unroll
            for (int j = 0; j < 2; j++) {          // two 16B chunks
                U8h uh, ul;
#pragma unroll
                for (int q = 0; q < 8; q++) {
                    const float f = vf[j * 8 + q];
                    const __half hi = __float2half_rn(f);
                    uh.h[q] = hi;
                    ul.h[q] = __float2half_rn(f - __half2float(hi));
                }
                const uint32_t sw = swz((uint32_t)arow * 128 + aq * 32 + j * 16);
                *reinterpret_cast<uint4*>(stPtr + sw) = uh.u;          // Ahi
                *reinterpret_cast<uint4*>(stPtr + TILEB + sw) = ul.u;  // Alo
            }
        }

        if (hasNext) { CP_WAIT1(); } else { CP_WAIT0(); }
        __syncthreads();

        // ---- compute chunk ----
        {
            // ldmatrix lane addressing
            const int amrow = wm * 32 + (lane & 15);
            const int akoff = (lane >> 4);               // 0/1 (16B chunk)
            const int bnrow = wn * 32 + (lane & 7) + ((lane >> 4) & 1) * 8;
            const int bkoff = (lane >> 3) & 1;
#pragma unroll
            for (int k16 = 0; k16 < 4; k16++) {
                uint32_t ah[2][4], al[2][4];
#pragma unroll
                for (int mi = 0; mi < 2; mi++) {
                    const uint32_t byteA =
                        (uint32_t)(amrow + mi * 16) * 128 + (k16 * 2 + akoff) * 16;
                    const uint32_t swA = swz(byteA);
                    ldsm4(ah[mi][0], ah[mi][1], ah[mi][2], ah[mi][3], stBase + swA);
                    ldsm4(al[mi][0], al[mi][1], al[mi][2], al[mi][3],
                          stBase + TILEB + swA);
                }
#pragma unroll
                for (int np = 0; np < 2; np++) {
                    const uint32_t byteB =
                        (uint32_t)(bnrow + np * 16) * 128 + (k16 * 2 + bkoff) * 16;
                    const uint32_t swB = swz(byteB);
                    uint32_t bh[4], bl[4];
                    ldsm4(bh[0], bh[1], bh[2], bh[3], stBase + 2 * TILEB + swB);
                    ldsm4(bl[0], bl[1], bl[2], bl[3], stBase + 3 * TILEB + swB);
#pragma unroll
                    for (int mi = 0; mi < 2; mi++) {
                        mma16816(acc[mi][np * 2],     ah[mi], bh);
                        mma16816(acc[mi][np * 2],     al[mi], bh);
                        mma16816(acc[mi][np * 2],     ah[mi], bl);
                        mma16816(acc[mi][np * 2 + 1], ah[mi], bh + 2);
                        mma16816(acc[mi][np * 2 + 1], al[mi], bh + 2);
                        mma16816(acc[mi][np * 2 + 1], ah[mi], bl + 2);
                    }
                }
            }
        }
        __syncthreads();
#pragma unroll
        for (int j = 0; j < 4; j++) ar[j] = arN[j];
    }

    // ---- store C -> g_hp[split], scale by 1/1024 ----
    {
        const float sc = 1.0f / 1024.0f;
        float* dst = g_hp[split];
#pragma unroll
        for (int mi = 0; mi < 2; mi++) {
            const int r0 = m0 + wm * 32 + mi * 16 + (lane >> 2);
            const int r1 = r0 + 8;
#pragma unroll
            for (int nf = 0; nf < 4; nf++) {
                const int col = wn * 32 + nf * 8 + 2 * (lane & 3);
                if (r0 < NN) {
                    float2 o = make_float2(acc[mi][nf][0] * sc, acc[mi][nf][1] * sc);
                    *reinterpret_cast<float2*>(&dst[(size_t)r0 * GEDIM + col]) = o;
                }
                if (r1 < NN) {
                    float2 o = make_float2(acc[mi][nf][2] * sc, acc[mi][nf][3] * sc);
                    *reinterpret_cast<float2*>(&dst[(size_t)r1 * GEDIM + col]) = o;
                }
            }
        }
    }
}

// ---------------------------------------------------------------------------
// Epilogue: 512 threads = 16 samples per block, weights staged in padded smem.
// ---------------------------------------------------------------------------
#define OFF_WE 0
#define OFF_WQ 66048
#define OFF_WK 74752
#define OFF_WV 83456
#define OFF_WO 92160
#define OFF_BE 100864
#define OFF_BQ 101376
#define OFF_BK 101888
#define OFF_BV 102400
#define OFF_BO 102912
#define OFF_BR 103424
#define OFF_H  103936
#define OFF_SC 112128
#define EPI_SMEM 124416

__global__ void __launch_bounds__(512) epilogue_kernel(
    const float* __restrict__ We, const float* __restrict__ be,
    const float* __restrict__ Wq, const float* __restrict__ bq,
    const float* __restrict__ Wk, const float* __restrict__ bk,
    const float* __restrict__ Wv, const float* __restrict__ bv,
    const float* __restrict__ Wo, const float* __restrict__ bo,
    const float* __restrict__ br,
    float* __restrict__ out)
{
    extern __shared__ char sm[];
    float* WE = reinterpret_cast<float*>(sm + OFF_WE);   // [128][129]
    float* WQ = reinterpret_cast<float*>(sm + OFF_WQ);   // [128][17]
    float* WK = reinterpret_cast<float*>(sm + OFF_WK);
    float* WV = reinterpret_cast<float*>(sm + OFF_WV);
    float* WO = reinterpret_cast<float*>(sm + OFF_WO);
    float* BE = reinterpret_cast<float*>(sm + OFF_BE);
    float* BQ = reinterpret_cast<float*>(sm + OFF_BQ);
    float* BK = reinterpret_cast<float*>(sm + OFF_BK);
    float* BV = reinterpret_cast<float*>(sm + OFF_BV);
    float* BO = reinterpret_cast<float*>(sm + OFF_BO);
    float* BR = reinterpret_cast<float*>(sm + OFF_BR);
    float* Hs = reinterpret_cast<float*>(sm + OFF_H);    // [16][128]
    float* SC = reinterpret_cast<float*>(sm + OFF_SC);   // 6 x [16][32]
    float* eoS = SC;
    float* qS  = SC + 512;
    float* kS  = SC + 1024;
    float* vS  = SC + 1536;
    float* aS  = SC + 2048;
    float* atS = SC + 2560;

    const int tid = threadIdx.x;

    for (int i = tid; i < 128 * 32; i += 512) {
        const int r = i >> 5;
        const int col = (i & 31) * 4;
        float4 w = *reinterpret_cast<const float4*>(We + (size_t)r * 128 + col);
        WE[r * 129 + col] = w.x; WE[r * 129 + col + 1] = w.y;
        WE[r * 129 + col + 2] = w.z; WE[r * 129 + col + 3] = w.w;
    }
    for (int i = tid; i < 2048; i += 512) {
        const int r = i >> 4;
        const int col = i & 15;
        WQ[r * 17 + col] = Wq[i];
        WK[r * 17 + col] = Wk[i];
        WV[r * 17 + col] = Wv[i];
        WO[r * 17 + col] = Wo[i];
    }
    if (tid < 128) {
        BE[tid] = be[tid]; BQ[tid] = bq[tid]; BK[tid] = bk[tid];
        BV[tid] = bv[tid]; BO[tid] = bo[tid]; BR[tid] = br[tid];
    }
    __syncthreads();

    const int warp = tid >> 5;
    const int lane = tid & 31;
    const int n = blockIdx.x * 16 + warp;

    // ---- h = sum of 4 partials + br ----
    float4 hv;
    {
        const float4* p0 = reinterpret_cast<const float4*>(&g_hp[0][(size_t)n * GEDIM]);
        const float4* p1 = reinterpret_cast<const float4*>(&g_hp[1][(size_t)n * GEDIM]);
        const float4* p2 = reinterpret_cast<const float4*>(&g_hp[2][(size_t)n * GEDIM]);
        const float4* p3 = reinterpret_cast<const float4*>(&g_hp[3][(size_t)n * GEDIM]);
        float4 a = p0[lane], b = p1[lane], cc = p2[lane], dd = p3[lane];
        hv.x = a.x + b.x + cc.x + dd.x + BR[lane * 4 + 0];
        hv.y = a.y + b.y + cc.y + dd.y + BR[lane * 4 + 1];
        hv.z = a.z + b.z + cc.z + dd.z + BR[lane * 4 + 2];
        hv.w = a.w + b.w + cc.w + dd.w + BR[lane * 4 + 3];
        *reinterpret_cast<float4*>(&Hs[warp * 128 + lane * 4]) = hv;
    }
    float v[4] = { hv.x, hv.y, hv.z, hv.w };

    // ---- top-1 ----
    float bval = v[0];
    int bidx = lane * 4;
#pragma unroll
    for (int t = 1; t < 4; t++)
        if (v[t] > bval) { bval = v[t]; bidx = lane * 4 + t; }
#pragma unroll
    for (int off = 16; off >= 1; off >>= 1) {
        float ov = __shfl_xor_sync(0xffffffffu, bval, off);
        int   oi = __shfl_xor_sync(0xffffffffu, bidx, off);
        if (ov > bval || (ov == bval && oi < bidx)) { bval = ov; bidx = oi; }
    }
    const float m1 = bval;
    const int   i1 = bidx;

    // ---- top-2 ----
    bval = -CUDART_INF_F;
    bidx = 1 << 30;
#pragma unroll
    for (int t = 0; t < 4; t++) {
        const int idx = lane * 4 + t;
        if (idx != i1 && v[t] > bval) { bval = v[t]; bidx = idx; }
    }
#pragma unroll
    for (int off = 16; off >= 1; off >>= 1) {
        float ov = __shfl_xor_sync(0xffffffffu, bval, off);
        int   oi = __shfl_xor_sync(0xffffffffu, bidx, off);
        if (ov > bval || (ov == bval && oi < bidx)) { bval = ov; bidx = oi; }
    }
    const float m2 = bval;
    const int   i2 = bidx;

    const float e2v = __expf(m2 - m1);
    const float inv = 1.0f / (1.0f + e2v);
    const float w1 = inv, w2 = e2v * inv;

    const int side   = lane >> 4;
    const int l      = lane & 15;
    const int target = side ? i2 : i1;
    const float wsel = side ? w2 : w1;
    const int g = target >> 4;
    const int f = target & 15;

    __syncwarp();

    // ---- eo for all 16 experts of selected group ----
    {
        const float* hrow = &Hs[warp * 128];
        const float* wrow = &WE[(g * 16 + l) * 129];
        float acc = BE[g * 16 + l];
#pragma unroll 8
        for (int k = 0; k < 128; k++) acc += hrow[k] * wrow[k];
        eoS[warp * 32 + lane] = acc;
    }
    __syncwarp();

    // ---- Q/K/V projections ----
    {
        const float* wqr = &WQ[(g * 16 + l) * 17];
        const float* wkr = &WK[(g * 16 + l) * 17];
        const float* wvr = &WV[(g * 16 + l) * 17];
        float q  = BQ[g * 16 + l];
        float kk = BK[g * 16 + l];
        float vv = BV[g * 16 + l];
#pragma unroll
        for (int e = 0; e < 16; e++) {
            const float eo = eoS[warp * 32 + side * 16 + e];
            q  += eo * wqr[e];
            kk += eo * wkr[e];
            vv += eo * wvr[e];
        }
        qS[warp * 32 + lane] = q;
        kS[warp * 32 + lane] = kk;
        vS[warp * 32 + lane] = vv;
    }
    __syncwarp();

    // ---- scores + softmax ----
    {
        const int d = l >> 2, e = l & 3;
        float s = 0.f;
#pragma unroll
        for (int h = 0; h < 4; h++)
            s += qS[warp * 32 + side * 16 + h * 4 + d] *
                 kS[warp * 32 + side * 16 + h * 4 + e];
        s *= 0.5f;
        float mx = s;
        mx = fmaxf(mx, __shfl_xor_sync(0xffffffffu, mx, 1));
        mx = fmaxf(mx, __shfl_xor_sync(0xffffffffu, mx, 2));
        float p = __expf(s - mx);
        float smv = p;
        smv += __shfl_xor_sync(0xffffffffu, smv, 1);
        smv += __shfl_xor_sync(0xffffffffu, smv, 2);
        p /= smv;
        aS[warp * 32 + lane] = p;
    }
    __syncwarp();

    // ---- att ----
    {
        const int h_ = l >> 2, dd = l & 3;
        float att = 0.f;
#pragma unroll
        for (int e = 0; e < 4; e++)
            att += aS[warp * 32 + side * 16 + dd * 4 + e] *
                   vS[warp * 32 + side * 16 + h_ * 4 + e];
        atS[warp * 32 + lane] = att;
    }
    __syncwarp();

    // ---- out + gate ----
    {
        const float* wor = &WO[(g * 16 + f) * 17];
        float t = atS[warp * 32 + side * 16 + l] * wor[l];
#pragma unroll
        for (int off = 8; off >= 1; off >>= 1)
            t += __shfl_xor_sync(0xffffffffu, t, off);
        t += BO[g * 16 + f];
        const float res = wsel * t;
        const float tot = res + __shfl_xor_sync(0xffffffffu, res, 16);
        if (lane == 0) out[n] = tot;
    }
}

// ---------------------------------------------------------------------------
extern "C" void kernel_launch(void* const* d_in, const int* in_sizes, int n_in,
                              void* d_out, int out_size)
{
    const float* x  = (const float*)d_in[0];
    const float* Wr = (const float*)d_in[1];
    const float* br = (const float*)d_in[2];
    const float* We = (const float*)d_in[3];
    const float* be = (const float*)d_in[4];
    const float* Wq = (const float*)d_in[5];
    const float* bq = (const float*)d_in[6];
    const float* Wk = (const float*)d_in[7];
    const float* bk = (const float*)d_in[8];
    const float* Wv = (const float*)d_in[9];
    const float* bv = (const float*)d_in[10];
    const float* Wo = (const float*)d_in[11];
    const float* bo = (const float*)d_in[12];
    float* out = (float*)d_out;

    static bool attr_done = false;
    if (!attr_done) {
        cudaFuncSetAttribute(gemm_kernel,
            cudaFuncAttributeMaxDynamicSharedMemorySize, GEMM_SMEM);
        cudaFuncSetAttribute(epilogue_kernel,
            cudaFuncAttributeMaxDynamicSharedMemorySize, EPI_SMEM);
        attr_done = true;
    }

    prep_kernel<<<NCH, 256>>>(Wr);
    gemm_kernel<<<dim3(157, 4), 512, GEMM_SMEM>>>(x);
    epilogue_kernel<<<1250, 512, EPI_SMEM>>>(We, be, Wq, bq, Wk, bk,
                                             Wv, bv, Wo, bo, br, out);
}

// round 5
// speedup vs baseline: 4.6884x; 1.0793x over previous
#include <cuda_runtime.h>
#include <cuda_fp16.h>
#include <math_constants.h>
#include <cstdint>

#define NN    20000
#define KDIM  9480
#define GEDIM 128
#define NCH   149          // ceil(9480/64)
#define BTILEB 16384       // one 128(n)x64(k) half tile, bytes
#define ATILEB 8192        // one 64(m)x64(k) half tile, bytes
// stage: Ahi(8K) Alo(8K) Bhi(16K) Blo(16K) = 48K
#define ST_AHI 0
#define ST_ALO 8192
#define ST_BHI 16384
#define ST_BLO 32768
#define STAGEB 49152
#define GEMM_SMEM (1024 + 2 * STAGEB)

// ---------------- static device scratch (no allocs) ----------------
__device__ float  g_hp[4][(size_t)NN * GEDIM];     // partial h per K-split
__device__ __half g_Bhi[(size_t)NCH * 8192];       // Wr^T hi, pre-swizzled chunks
__device__ __half g_Blo[(size_t)NCH * 8192];       // Wr^T lo

// ---------------- helpers ----------------
__device__ __forceinline__ uint32_t smem_u32(const void* p) {
    uint32_t a;
    asm("{ .reg .u64 t; cvta.to.shared.u64 t, %1; cvt.u32.u64 %0, t; }"
        : "=r"(a) : "l"(p));
    return a;
}
__device__ __forceinline__ uint32_t swz(uint32_t b) { return b ^ ((b >> 3) & 0x70); }

__device__ __forceinline__ void ldsm4(uint32_t& r0, uint32_t& r1,
                                      uint32_t& r2, uint32_t& r3, uint32_t a) {
    asm volatile("ldmatrix.sync.aligned.m8n8.x4.shared.b16 {%0,%1,%2,%3}, [%4];"
                 : "=r"(r0), "=r"(r1), "=r"(r2), "=r"(r3) : "r"(a));
}
__device__ __forceinline__ void mma16816(float* c, const uint32_t* a,
                                         const uint32_t* b) {
    asm volatile(
        "mma.sync.aligned.m16n8k16.row.col.f32.f16.f16.f32 "
        "{%0,%1,%2,%3},{%4,%5,%6,%7},{%8,%9},{%0,%1,%2,%3};"
        : "+f"(c[0]), "+f"(c[1]), "+f"(c[2]), "+f"(c[3])
        : "r"(a[0]), "r"(a[1]), "r"(a[2]), "r"(a[3]), "r"(b[0]), "r"(b[1]));
}
#define CP16(dst, src) \
    asm volatile("cp.async.ca.shared.global [%0], [%1], 16;" \
                 :: "r"(dst), "l"(src) : "memory")
#define CP_COMMIT() asm volatile("cp.async.commit_group;" ::: "memory")
#define CP_WAIT1()  asm volatile("cp.async.wait_group 1;" ::: "memory")
#define CP_WAIT0()  asm volatile("cp.async.wait_group 0;" ::: "memory")

union U8h { __half h[8]; uint4 u; };

// ---------------------------------------------------------------------------
// Prep: g_Bhi/g_Blo = transpose(Wr)*1024, split hi/lo, per-chunk swizzled
// 128(n) x 64(k) half tiles. One block per chunk.
// ---------------------------------------------------------------------------
__global__ void __launch_bounds__(256) prep_kernel(const float* __restrict__ Wr)
{
    __shared__ float Ws[64][128];
    const int c = blockIdx.x;
    const int tid = threadIdx.x;

    for (int i = tid; i < 64 * 32; i += 256) {
        const int r = i >> 5;
        const int col = (i & 31) * 4;
        const int gk = c * 64 + r;
        float4 v = make_float4(0.f, 0.f, 0.f, 0.f);
        if (gk < KDIM) v = *reinterpret_cast<const float4*>(Wr + (size_t)gk * GEDIM + col);
        Ws[r][col] = v.x; Ws[r][col + 1] = v.y; Ws[r][col + 2] = v.z; Ws[r][col + 3] = v.w;
    }
    __syncthreads();

    const int n = tid & 127;
    const int sel = tid >> 7;     // 0 -> hi, 1 -> lo
    char* dstBase = reinterpret_cast<char*>(sel ? g_Blo : g_Bhi) + (size_t)c * BTILEB;

    for (int grp = 0; grp < 8; grp++) {
        U8h u;
#pragma unroll
        for (int j = 0; j < 8; j++) {
            const float f = Ws[grp * 8 + j][n] * 1024.0f;
            const __half hi = __float2half_rn(f);
            u.h[j] = sel ? __float2half_rn(f - __half2float(hi)) : hi;
        }
        const uint32_t byte = (uint32_t)n * 128 + grp * 16;
        *reinterpret_cast<uint4*>(dstBase + swz(byte)) = u.u;
    }
}

// ---------------------------------------------------------------------------
// GEMM via mma.sync m16n8k16, fp16 3-product split, fp32 accum.
// grid (313, 4); 256 threads; 64x128 tile; K chunks of 64; 2-stage pipeline;
// 2 CTAs per SM.
// ---------------------------------------------------------------------------
__global__ void __launch_bounds__(256, 2) gemm_kernel(const float* __restrict__ x)
{
    extern __shared__ char smem[];
    const uint32_t sb = smem_u32(smem) + 1024;
    char* const stg0 = smem + 1024;

    const int tid  = threadIdx.x;
    const int wid  = tid >> 5;
    const int lane = tid & 31;
    const int wm   = wid & 1;         // M half (32 rows)
    const int wn   = wid >> 1;        // N quadrant (32 cols)
    const int m0   = blockIdx.x * 64;
    const int split = blockIdx.y;
    const int c0 = split * 38;
    const int c1 = (c0 + 38 < NCH) ? c0 + 38 : NCH;
    const int nrel = c1 - c0;

    // A producer mapping: 256 threads -> 64 rows x 4 k-quarters (16 floats each)
    const int arow = tid >> 2;
    const int aq   = tid & 3;
    const bool rowOk = (m0 + arow) < NN;
    const float* xrow = x + (size_t)(m0 + arow) * KDIM;

    // B producer mapping: 64B of hi + 64B of lo per thread
    const uint32_t bOff = (uint32_t)tid * 64;

    float acc[2][4][4];
#pragma unroll
    for (int i = 0; i < 2; i++)
#pragma unroll
        for (int j = 0; j < 4; j++)
#pragma unroll
            for (int q = 0; q < 4; q++) acc[i][j][q] = 0.f;

    // ---- prologue: B(c0) cp.async, A(c0) LDG ----
    {
        const char* srcH = reinterpret_cast<const char*>(g_Bhi) + (size_t)c0 * BTILEB + bOff;
        const char* srcL = reinterpret_cast<const char*>(g_Blo) + (size_t)c0 * BTILEB + bOff;
#pragma unroll
        for (int q = 0; q < 4; q++) {
            CP16(sb + ST_BHI + bOff + q * 16, srcH + q * 16);
            CP16(sb + ST_BLO + bOff + q * 16, srcL + q * 16);
        }
        CP_COMMIT();
    }
    float4 ar[4];
    {
        const int kb = c0 * 64 + aq * 16;
#pragma unroll
        for (int j = 0; j < 4; j++) {
            ar[j] = make_float4(0.f, 0.f, 0.f, 0.f);
            if (rowOk && kb + j * 4 < KDIM)
                ar[j] = *reinterpret_cast<const float4*>(xrow + kb + j * 4);
        }
    }

    for (int rc = 0; rc < nrel; ++rc) {
        const int s = rc & 1;
        const uint32_t stBase = sb + s * STAGEB;
        char* const stPtr = stg0 + s * STAGEB;
        const bool hasNext = (rc + 1) < nrel;

        float4 arN[4];
        if (hasNext) {
            const int cn = c0 + rc + 1;
            const uint32_t st2 = sb + (s ^ 1) * STAGEB;
            const char* srcH = reinterpret_cast<const char*>(g_Bhi) + (size_t)cn * BTILEB + bOff;
            const char* srcL = reinterpret_cast<const char*>(g_Blo) + (size_t)cn * BTILEB + bOff;
#pragma unroll
            for (int q = 0; q < 4; q++) {
                CP16(st2 + ST_BHI + bOff + q * 16, srcH + q * 16);
                CP16(st2 + ST_BLO + bOff + q * 16, srcL + q * 16);
            }
            CP_COMMIT();
            const int kb = cn * 64 + aq * 16;
#pragma unroll
            for (int j = 0; j < 4; j++) {
                arN[j] = make_float4(0.f, 0.f, 0.f, 0.f);
                if (rowOk && kb + j * 4 < KDIM)
                    arN[j] = *reinterpret_cast<const float4*>(xrow + kb + j * 4);
            }
        }

        // ---- STS A(rc): split fp32 -> fp16 hi/lo, swizzled ----
        {
            const float* vf = reinterpret_cast<const float*>(ar);
#pragma unroll
            for (int j = 0; j < 2; j++) {          // two 16B chunks
                U8h uh, ul;
#pragma unroll
                for (int q = 0; q < 8; q++) {
                    const float f = vf[j * 8 + q];
                    const __half hi = __float2half_rn(f);
                    uh.h[q] = hi;
                    ul.h[q] = __float2half_rn(f - __half2float(hi));
                }
                const uint32_t sw = swz((uint32_t)arow * 128 + aq * 32 + j * 16);
                *reinterpret_cast<uint4*>(stPtr + ST_AHI + sw) = uh.u;
                *reinterpret_cast<uint4*>(stPtr + ST_ALO + sw) = ul.u;
            }
        }

        if (hasNext) { CP_WAIT1(); } else { CP_WAIT0(); }
        __syncthreads();

        // ---- compute chunk ----
        {
            const int amrow = wm * 32 + (lane & 15);
            const int akoff = (lane >> 4);               // 0/1 (16B chunk)
            const int bnrow = wn * 32 + (lane & 7) + ((lane >> 4) & 1) * 8;
            const int bkoff = (lane >> 3) & 1;
#pragma unroll
            for (int k16 = 0; k16 < 4; k16++) {
                uint32_t ah[2][4], al[2][4];
#pragma unroll
                for (int mi = 0; mi < 2; mi++) {
                    const uint32_t byteA =
                        (uint32_t)(amrow + mi * 16) * 128 + (k16 * 2 + akoff) * 16;
                    const uint32_t swA = swz(byteA);
                    ldsm4(ah[mi][0], ah[mi][1], ah[mi][2], ah[mi][3],
                          stBase + ST_AHI + swA);
                    ldsm4(al[mi][0], al[mi][1], al[mi][2], al[mi][3],
                          stBase + ST_ALO + swA);
                }
#pragma unroll
                for (int np = 0; np < 2; np++) {
                    const uint32_t byteB =
                        (uint32_t)(bnrow + np * 16) * 128 + (k16 * 2 + bkoff) * 16;
                    const uint32_t swB = swz(byteB);
                    uint32_t bh[4], bl[4];
                    ldsm4(bh[0], bh[1], bh[2], bh[3], stBase + ST_BHI + swB);
                    ldsm4(bl[0], bl[1], bl[2], bl[3], stBase + ST_BLO + swB);
#pragma unroll
                    for (int mi = 0; mi < 2; mi++) {
                        mma16816(acc[mi][np * 2],     ah[mi], bh);
                        mma16816(acc[mi][np * 2],     al[mi], bh);
                        mma16816(acc[mi][np * 2],     ah[mi], bl);
                        mma16816(acc[mi][np * 2 + 1], ah[mi], bh + 2);
                        mma16816(acc[mi][np * 2 + 1], al[mi], bh + 2);
                        mma16816(acc[mi][np * 2 + 1], ah[mi], bl + 2);
                    }
                }
            }
        }
        __syncthreads();
#pragma unroll
        for (int j = 0; j < 4; j++) ar[j] = arN[j];
    }

    // ---- store C -> g_hp[split], scale by 1/1024 ----
    {
        const float sc = 1.0f / 1024.0f;
        float* dst = g_hp[split];
#pragma unroll
        for (int mi = 0; mi < 2; mi++) {
            const int r0 = m0 + wm * 32 + mi * 16 + (lane >> 2);
            const int r1 = r0 + 8;
#pragma unroll
            for (int nf = 0; nf < 4; nf++) {
                const int col = wn * 32 + nf * 8 + 2 * (lane & 3);
                if (r0 < NN) {
                    float2 o = make_float2(acc[mi][nf][0] * sc, acc[mi][nf][1] * sc);
                    *reinterpret_cast<float2*>(&dst[(size_t)r0 * GEDIM + col]) = o;
                }
                if (r1 < NN) {
                    float2 o = make_float2(acc[mi][nf][2] * sc, acc[mi][nf][3] * sc);
                    *reinterpret_cast<float2*>(&dst[(size_t)r1 * GEDIM + col]) = o;
                }
            }
        }
    }
}

// ---------------------------------------------------------------------------
// Epilogue: 512 threads = 16 samples per block, weights staged in padded smem.
// ---------------------------------------------------------------------------
#define OFF_WE 0
#define OFF_WQ 66048
#define OFF_WK 74752
#define OFF_WV 83456
#define OFF_WO 92160
#define OFF_BE 100864
#define OFF_BQ 101376
#define OFF_BK 101888
#define OFF_BV 102400
#define OFF_BO 102912
#define OFF_BR 103424
#define OFF_H  103936
#define OFF_SC 112128
#define EPI_SMEM 124416

__global__ void __launch_bounds__(512) epilogue_kernel(
    const float* __restrict__ We, const float* __restrict__ be,
    const float* __restrict__ Wq, const float* __restrict__ bq,
    const float* __restrict__ Wk, const float* __restrict__ bk,
    const float* __restrict__ Wv, const float* __restrict__ bv,
    const float* __restrict__ Wo, const float* __restrict__ bo,
    const float* __restrict__ br,
    float* __restrict__ out)
{
    extern __shared__ char sm[];
    float* WE = reinterpret_cast<float*>(sm + OFF_WE);   // [128][129]
    float* WQ = reinterpret_cast<float*>(sm + OFF_WQ);   // [128][17]
    float* WK = reinterpret_cast<float*>(sm + OFF_WK);
    float* WV = reinterpret_cast<float*>(sm + OFF_WV);
    float* WO = reinterpret_cast<float*>(sm + OFF_WO);
    float* BE = reinterpret_cast<float*>(sm + OFF_BE);
    float* BQ = reinterpret_cast<float*>(sm + OFF_BQ);
    float* BK = reinterpret_cast<float*>(sm + OFF_BK);
    float* BV = reinterpret_cast<float*>(sm + OFF_BV);
    float* BO = reinterpret_cast<float*>(sm + OFF_BO);
    float* BR = reinterpret_cast<float*>(sm + OFF_BR);
    float* Hs = reinterpret_cast<float*>(sm + OFF_H);    // [16][128]
    float* SC = reinterpret_cast<float*>(sm + OFF_SC);   // 6 x [16][32]
    float* eoS = SC;
    float* qS  = SC + 512;
    float* kS  = SC + 1024;
    float* vS  = SC + 1536;
    float* aS  = SC + 2048;
    float* atS = SC + 2560;

    const int tid = threadIdx.x;

    for (int i = tid; i < 128 * 32; i += 512) {
        const int r = i >> 5;
        const int col = (i & 31) * 4;
        float4 w = *reinterpret_cast<const float4*>(We + (size_t)r * 128 + col);
        WE[r * 129 + col] = w.x; WE[r * 129 + col + 1] = w.y;
        WE[r * 129 + col + 2] = w.z; WE[r * 129 + col + 3] = w.w;
    }
    for (int i = tid; i < 2048; i += 512) {
        const int r = i >> 4;
        const int col = i & 15;
        WQ[r * 17 + col] = Wq[i];
        WK[r * 17 + col] = Wk[i];
        WV[r * 17 + col] = Wv[i];
        WO[r * 17 + col] = Wo[i];
    }
    if (tid < 128) {
        BE[tid] = be[tid]; BQ[tid] = bq[tid]; BK[tid] = bk[tid];
        BV[tid] = bv[tid]; BO[tid] = bo[tid]; BR[tid] = br[tid];
    }
    __syncthreads();

    const int warp = tid >> 5;
    const int lane = tid & 31;
    const int n = blockIdx.x * 16 + warp;

    // ---- h = sum of 4 partials + br ----
    float4 hv;
    {
        const float4* p0 = reinterpret_cast<const float4*>(&g_hp[0][(size_t)n * GEDIM]);
        const float4* p1 = reinterpret_cast<const float4*>(&g_hp[1][(size_t)n * GEDIM]);
        const float4* p2 = reinterpret_cast<const float4*>(&g_hp[2][(size_t)n * GEDIM]);
        const float4* p3 = reinterpret_cast<const float4*>(&g_hp[3][(size_t)n * GEDIM]);
        float4 a = p0[lane], b = p1[lane], cc = p2[lane], dd = p3[lane];
        hv.x = a.x + b.x + cc.x + dd.x + BR[lane * 4 + 0];
        hv.y = a.y + b.y + cc.y + dd.y + BR[lane * 4 + 1];
        hv.z = a.z + b.z + cc.z + dd.z + BR[lane * 4 + 2];
        hv.w = a.w + b.w + cc.w + dd.w + BR[lane * 4 + 3];
        *reinterpret_cast<float4*>(&Hs[warp * 128 + lane * 4]) = hv;
    }
    float v[4] = { hv.x, hv.y, hv.z, hv.w };

    // ---- top-1 ----
    float bval = v[0];
    int bidx = lane * 4;
#pragma unroll
    for (int t = 1; t < 4; t++)
        if (v[t] > bval) { bval = v[t]; bidx = lane * 4 + t; }
#pragma unroll
    for (int off = 16; off >= 1; off >>= 1) {
        float ov = __shfl_xor_sync(0xffffffffu, bval, off);
        int   oi = __shfl_xor_sync(0xffffffffu, bidx, off);
        if (ov > bval || (ov == bval && oi < bidx)) { bval = ov; bidx = oi; }
    }
    const float m1 = bval;
    const int   i1 = bidx;

    // ---- top-2 ----
    bval = -CUDART_INF_F;
    bidx = 1 << 30;
#pragma unroll
    for (int t = 0; t < 4; t++) {
        const int idx = lane * 4 + t;
        if (idx != i1 && v[t] > bval) { bval = v[t]; bidx = idx; }
    }
#pragma unroll
    for (int off = 16; off >= 1; off >>= 1) {
        float ov = __shfl_xor_sync(0xffffffffu, bval, off);
        int   oi = __shfl_xor_sync(0xffffffffu, bidx, off);
        if (ov > bval || (ov == bval && oi < bidx)) { bval = ov; bidx = oi; }
    }
    const float m2 = bval;
    const int   i2 = bidx;

    const float e2v = __expf(m2 - m1);
    const float inv = 1.0f / (1.0f + e2v);
    const float w1 = inv, w2 = e2v * inv;

    const int side   = lane >> 4;
    const int l      = lane & 15;
    const int target = side ? i2 : i1;
    const float wsel = side ? w2 : w1;
    const int g = target >> 4;
    const int f = target & 15;

    __syncwarp();

    // ---- eo for all 16 experts of selected group ----
    {
        const float* hrow = &Hs[warp * 128];
        const float* wrow = &WE[(g * 16 + l) * 129];
        float acc = BE[g * 16 + l];
#pragma unroll 8
        for (int k = 0; k < 128; k++) acc += hrow[k] * wrow[k];
        eoS[warp * 32 + lane] = acc;
    }
    __syncwarp();

    // ---- Q/K/V projections ----
    {
        const float* wqr = &WQ[(g * 16 + l) * 17];
        const float* wkr = &WK[(g * 16 + l) * 17];
        const float* wvr = &WV[(g * 16 + l) * 17];
        float q  = BQ[g * 16 + l];
        float kk = BK[g * 16 + l];
        float vv = BV[g * 16 + l];
#pragma unroll
        for (int e = 0; e < 16; e++) {
            const float eo = eoS[warp * 32 + side * 16 + e];
            q  += eo * wqr[e];
            kk += eo * wkr[e];
            vv += eo * wvr[e];
        }
        qS[warp * 32 + lane] = q;
        kS[warp * 32 + lane] = kk;
        vS[warp * 32 + lane] = vv;
    }
    __syncwarp();

    // ---- scores + softmax ----
    {
        const int d = l >> 2, e = l & 3;
        float s = 0.f;
#pragma unroll
        for (int h = 0; h < 4; h++)
            s += qS[warp * 32 + side * 16 + h * 4 + d] *
                 kS[warp * 32 + side * 16 + h * 4 + e];
        s *= 0.5f;
        float mx = s;
        mx = fmaxf(mx, __shfl_xor_sync(0xffffffffu, mx, 1));
        mx = fmaxf(mx, __shfl_xor_sync(0xffffffffu, mx, 2));
        float p = __expf(s - mx);
        float smv = p;
        smv += __shfl_xor_sync(0xffffffffu, smv, 1);
        smv += __shfl_xor_sync(0xffffffffu, smv, 2);
        p /= smv;
        aS[warp * 32 + lane] = p;
    }
    __syncwarp();

    // ---- att ----
    {
        const int h_ = l >> 2, dd = l & 3;
        float att = 0.f;
#pragma unroll
        for (int e = 0; e < 4; e++)
            att += aS[warp * 32 + side * 16 + dd * 4 + e] *
                   vS[warp * 32 + side * 16 + h_ * 4 + e];
        atS[warp * 32 + lane] = att;
    }
    __syncwarp();

    // ---- out + gate ----
    {
        const float* wor = &WO[(g * 16 + f) * 17];
        float t = atS[warp * 32 + side * 16 + l] * wor[l];
#pragma unroll
        for (int off = 8; off >= 1; off >>= 1)
            t += __shfl_xor_sync(0xffffffffu, t, off);
        t += BO[g * 16 + f];
        const float res = wsel * t;
        const float tot = res + __shfl_xor_sync(0xffffffffu, res, 16);
        if (lane == 0) out[n] = tot;
    }
}

// ---------------------------------------------------------------------------
extern "C" void kernel_launch(void* const* d_in, const int* in_sizes, int n_in,
                              void* d_out, int out_size)
{
    const float* x  = (const float*)d_in[0];
    const float* Wr = (const float*)d_in[1];
    const float* br = (const float*)d_in[2];
    const float* We = (const float*)d_in[3];
    const float* be = (const float*)d_in[4];
    const float* Wq = (const float*)d_in[5];
    const float* bq = (const float*)d_in[6];
    const float* Wk = (const float*)d_in[7];
    const float* bk = (const float*)d_in[8];
    const float* Wv = (const float*)d_in[9];
    const float* bv = (const float*)d_in[10];
    const float* Wo = (const float*)d_in[11];
    const float* bo = (const float*)d_in[12];
    float* out = (float*)d_out;

    static bool attr_done = false;
    if (!attr_done) {
        cudaFuncSetAttribute(gemm_kernel,
            cudaFuncAttributeMaxDynamicSharedMemorySize, GEMM_SMEM);
        cudaFuncSetAttribute(epilogue_kernel,
            cudaFuncAttributeMaxDynamicSharedMemorySize, EPI_SMEM);
        attr_done = true;
    }

    prep_kernel<<<NCH, 256>>>(Wr);
    gemm_kernel<<<dim3(313, 4), 256, GEMM_SMEM>>>(x);
    epilogue_kernel<<<1250, 512, EPI_SMEM>>>(We, be, Wq, bq, Wk, bk,
                                             Wv, bv, Wo, bo, br, out);
}